// round 6
// baseline (speedup 1.0000x reference)
#include <cuda_runtime.h>
#include <cstdint>
#include <cstddef>

// ---------------- scratch ----------------
__device__ float g_Q[4096u * 4096u];
__device__ float g_K[4096u * 1024u];
__device__ float g_V[4096u * 1024u];
__device__ float g_ctx[4096u * 4096u];

// ---------------- helpers ----------------
__device__ __forceinline__ uint32_t f2tf(float x) {
    uint32_t u;
    asm("cvt.rna.tf32.f32 %0, %1;" : "=r"(u) : "f"(x));
    return u;
}
__device__ __forceinline__ float4 tf4(float4 v) {
    float4 t;
    t.x = __uint_as_float(f2tf(v.x)); t.y = __uint_as_float(f2tf(v.y));
    t.z = __uint_as_float(f2tf(v.z)); t.w = __uint_as_float(f2tf(v.w));
    return t;
}
__device__ __forceinline__ uint32_t smem_u32(const void* p) {
    uint32_t a;
    asm("{ .reg .u64 t; cvta.to.shared.u64 t, %1; cvt.u32.u64 %0, t; }" : "=r"(a) : "l"(p));
    return a;
}
__device__ __forceinline__ void mma_tf32(float* c, uint32_t a0, uint32_t a1,
                                         uint32_t a2, uint32_t a3,
                                         uint32_t b0, uint32_t b1) {
    asm volatile(
        "mma.sync.aligned.m16n8k8.row.col.f32.tf32.tf32.f32 "
        "{%0,%1,%2,%3}, {%4,%5,%6,%7}, {%8,%9}, {%0,%1,%2,%3};\n"
        : "+f"(c[0]), "+f"(c[1]), "+f"(c[2]), "+f"(c[3])
        : "r"(a0), "r"(a1), "r"(a2), "r"(a3), "r"(b0), "r"(b1));
}
#define CP_ASYNC16(dst, src) \
    asm volatile("cp.async.cg.shared.global [%0], [%1], 16;" :: "r"(dst), "l"(src) : "memory")
#define CP_COMMIT() asm volatile("cp.async.commit_group;" ::: "memory")
#define CP_WAIT2()  asm volatile("cp.async.wait_group 2;" ::: "memory")

// =========================================================================
// TF32 GEMM v3 (cp.async 4-stage):  C[M,N] = A[M,K] @ B[N,K]^T
// Block 128x128, K-tile 32, 256 threads (8 warps: 2 in M x 4 in N),
// warp tile 64x32. Raw fp32 in smem; cvt.rna at fragment load.
// =========================================================================
#define GA_STR 36                       // 32 + 4 pad floats (row = 144B, 16B-aligned)
#define NST 4
#define STGF (2 * 128 * GA_STR)         // floats per stage (A then B)
#define GEMM_SMEM (NST * STGF * 4)      // 147456 bytes

__global__ void __launch_bounds__(256)
gemm_tf32(float* __restrict__ C, const float* __restrict__ A,
          const float* __restrict__ B, int M, int N, int K)
{
    extern __shared__ float sm[];

    const int tid  = threadIdx.x;
    const int warp = tid >> 5, lane = tid & 31;
    const int wm = warp & 1, wn = warp >> 1;
    const int bm = blockIdx.y * 128, bn = blockIdx.x * 128;
    const int kTiles = K >> 5;

    // per-thread cp.async targets: A: 4 chunks, B: 4 chunks (16B each)
    const int r8 = tid >> 3;            // 0..31  (row group base)
    const int c8 = tid & 7;             // 0..7   (16B chunk in row)
    const uint32_t sbase = smem_u32(sm);

    auto issue = [&](int kt) {
        const int s = kt & (NST - 1);
        const uint32_t As = sbase + (uint32_t)(s * STGF) * 4;
        const uint32_t Bs = As + 128 * GA_STR * 4;
        const float* Ag = A + (size_t)bm * K + (size_t)kt * 32;
        const float* Bg = B + (size_t)bn * K + (size_t)kt * 32;
#pragma unroll
        for (int i = 0; i < 4; i++) {
            int r = r8 + i * 32;
            CP_ASYNC16(As + (uint32_t)(r * GA_STR + c8 * 4) * 4,
                       Ag + (size_t)r * K + c8 * 4);
        }
#pragma unroll
        for (int i = 0; i < 4; i++) {
            int r = r8 + i * 32;
            CP_ASYNC16(Bs + (uint32_t)(r * GA_STR + c8 * 4) * 4,
                       Bg + (size_t)r * K + c8 * 4);
        }
        CP_COMMIT();
    };

    float acc[4][4][4];
#pragma unroll
    for (int i = 0; i < 4; i++)
#pragma unroll
        for (int j = 0; j < 4; j++)
#pragma unroll
            for (int t = 0; t < 4; t++) acc[i][j][t] = 0.f;

    issue(0); issue(1); issue(2);

    for (int kt = 0; kt < kTiles; kt++) {
        CP_WAIT2();
        __syncthreads();
        if (kt + 3 < kTiles) issue(kt + 3);
        else CP_COMMIT();                       // keep group count in lockstep

        const float* As_ = sm + (kt & (NST - 1)) * STGF;
        const float* Bs_ = As_ + 128 * GA_STR;
#pragma unroll
        for (int ks = 0; ks < 32; ks += 8) {
            uint32_t a[4][4], b[4][2];
#pragma unroll
            for (int mt = 0; mt < 4; mt++) {
                int r0 = wm * 64 + mt * 16 + (lane >> 2);
                int c0 = ks + (lane & 3);
                a[mt][0] = f2tf(As_[r0 * GA_STR + c0]);
                a[mt][1] = f2tf(As_[(r0 + 8) * GA_STR + c0]);
                a[mt][2] = f2tf(As_[r0 * GA_STR + c0 + 4]);
                a[mt][3] = f2tf(As_[(r0 + 8) * GA_STR + c0 + 4]);
            }
#pragma unroll
            for (int nt = 0; nt < 4; nt++) {
                int n0 = wn * 32 + nt * 8 + (lane >> 2);
                int k0 = ks + (lane & 3);
                b[nt][0] = f2tf(Bs_[n0 * GA_STR + k0]);
                b[nt][1] = f2tf(Bs_[n0 * GA_STR + k0 + 4]);
            }
#pragma unroll
            for (int mt = 0; mt < 4; mt++)
#pragma unroll
                for (int nt = 0; nt < 4; nt++)
                    mma_tf32(acc[mt][nt], a[mt][0], a[mt][1], a[mt][2], a[mt][3],
                             b[nt][0], b[nt][1]);
        }
        __syncthreads();
    }

#pragma unroll
    for (int mt = 0; mt < 4; mt++) {
        int r0 = bm + wm * 64 + mt * 16 + (lane >> 2);
#pragma unroll
        for (int nt = 0; nt < 4; nt++) {
            int c0 = bn + wn * 32 + nt * 8 + ((lane & 3) << 1);
            float* c = acc[mt][nt];
            *(float2*)(C + (size_t)r0 * N + c0)       = make_float2(c[0], c[1]);
            *(float2*)(C + (size_t)(r0 + 8) * N + c0) = make_float2(c[2], c[3]);
        }
    }
}

// =========================================================================
// Fused RoPE: Q heads (0..31) and K heads (32..39) in one launch.
// grid (4096, 10), block (64, 4).
// =========================================================================
__global__ void rope_all(float* __restrict__ Q, float* __restrict__ K)
{
    int tok = blockIdx.x;
    int hh  = blockIdx.y * 4 + threadIdx.y;     // 0..39
    int d   = threadIdx.x;                      // 0..63
    int s   = tok & 2047;
    // inv_freq = 10000^(-d/64) = exp2(-d * log2(10000)/64)
    float inv = exp2f((float)d * -0.20762050593046f);
    float ang = (float)s * inv;
    float sn, cs;
    sincosf(ang, &sn, &cs);
    float* p = (hh < 32) ? (Q + (size_t)tok * 4096 + hh * 128)
                         : (K + (size_t)tok * 1024 + (hh - 32) * 128);
    float x1 = p[d], x2 = p[d + 64];
    p[d]      = x1 * cs - x2 * sn;
    p[d + 64] = x2 * cs + x1 * sn;
}

// =========================================================================
// Causal flash attention with tf32 mma (unchanged from R4)
// =========================================================================
#define QS_STR 132
#define VS_STR 136
#define SS_STR 68

__global__ void __launch_bounds__(256)
attn_kernel(float* __restrict__ ctx, const float* __restrict__ Qg,
            const float* __restrict__ Kg, const float* __restrict__ Vg)
{
    extern __shared__ float sm[];
    float* Qs   = sm;
    float* Ks   = Qs + 64 * QS_STR;
    float* Vs   = Ks + 64 * QS_STR;
    float* Ss   = Vs + 64 * VS_STR;
    float* m_sm = Ss + 64 * SS_STR;
    float* l_sm = m_sm + 64;
    float* a_sm = l_sm + 64;

    const int tid  = threadIdx.x;
    const int warp = tid >> 5, lane = tid & 31;
    const int lq = lane >> 2;
    const int lr = lane & 3;
    const int qt = 31 - (int)blockIdx.x;
    const int h  = blockIdx.y;
    const int b  = blockIdx.z;
    const int hkv = h >> 2;
    const float scale = 0.08838834764831845f;

    const int mq = warp & 3;
    const int wh = warp >> 2;

    const float* Qp = Qg + ((size_t)(b * 2048 + qt * 64)) * 4096 + h * 128;
#pragma unroll
    for (int i = 0; i < 8; i++) {
        int f = tid + i * 256;
        int r = f >> 5, c4 = (f & 31) << 2;
        float4 v = *(const float4*)(Qp + (size_t)r * 4096 + c4);
        v.x *= scale; v.y *= scale; v.z *= scale; v.w *= scale;
        *(float4*)(Qs + r * QS_STR + c4) = tf4(v);
    }
    if (tid < 64) { m_sm[tid] = -3.0e38f; l_sm[tid] = 0.f; }

    float O[8][4];
#pragma unroll
    for (int i = 0; i < 8; i++)
#pragma unroll
        for (int j = 0; j < 4; j++) O[i][j] = 0.f;

    __syncthreads();

    for (int kt = 0; kt <= qt; kt++) {
        const float* Kp = Kg + ((size_t)(b * 2048 + kt * 64)) * 1024 + hkv * 128;
        const float* Vp = Vg + ((size_t)(b * 2048 + kt * 64)) * 1024 + hkv * 128;
#pragma unroll
        for (int i = 0; i < 8; i++) {
            int f = tid + i * 256;
            int r = f >> 5, c4 = (f & 31) << 2;
            *(float4*)(Ks + r * QS_STR + c4) = tf4(*(const float4*)(Kp + (size_t)r * 1024 + c4));
            *(float4*)(Vs + r * VS_STR + c4) = tf4(*(const float4*)(Vp + (size_t)r * 1024 + c4));
        }
        __syncthreads();

        {
            float sacc[4][4];
#pragma unroll
            for (int nt = 0; nt < 4; nt++)
#pragma unroll
                for (int t = 0; t < 4; t++) sacc[nt][t] = 0.f;

            const int r0 = mq * 16 + lq;
#pragma unroll
            for (int ks = 0; ks < 128; ks += 8) {
                int c0 = ks + lr;
                uint32_t a0 = __float_as_uint(Qs[r0 * QS_STR + c0]);
                uint32_t a1 = __float_as_uint(Qs[(r0 + 8) * QS_STR + c0]);
                uint32_t a2 = __float_as_uint(Qs[r0 * QS_STR + c0 + 4]);
                uint32_t a3 = __float_as_uint(Qs[(r0 + 8) * QS_STR + c0 + 4]);
#pragma unroll
                for (int nt = 0; nt < 4; nt++) {
                    int n0 = wh * 32 + nt * 8 + lq;
                    uint32_t b0 = __float_as_uint(Ks[n0 * QS_STR + c0]);
                    uint32_t b1 = __float_as_uint(Ks[n0 * QS_STR + c0 + 4]);
                    mma_tf32(sacc[nt], a0, a1, a2, a3, b0, b1);
                }
            }
            bool diag = (kt == qt);
#pragma unroll
            for (int nt = 0; nt < 4; nt++) {
                int c = wh * 32 + nt * 8 + 2 * lr;
                float v0 = sacc[nt][0], v1 = sacc[nt][1];
                float v2 = sacc[nt][2], v3 = sacc[nt][3];
                int ra = mq * 16 + lq, rb2 = ra + 8;
                if (diag) {
                    if (c > ra)      v0 = -3.0e38f;
                    if (c + 1 > ra)  v1 = -3.0e38f;
                    if (c > rb2)     v2 = -3.0e38f;
                    if (c + 1 > rb2) v3 = -3.0e38f;
                }
                *(float2*)(Ss + ra * SS_STR + c)  = make_float2(v0, v1);
                *(float2*)(Ss + rb2 * SS_STR + c) = make_float2(v2, v3);
            }
        }
        __syncthreads();

        {
            int row = tid >> 2, seg = tid & 3;
            float* srow = Ss + row * SS_STR;
            float mx = -3.0e38f;
#pragma unroll
            for (int c = 0; c < 16; c++) mx = fmaxf(mx, srow[seg * 16 + c]);
            mx = fmaxf(mx, __shfl_xor_sync(0xffffffffu, mx, 1));
            mx = fmaxf(mx, __shfl_xor_sync(0xffffffffu, mx, 2));
            float m_old = m_sm[row];
            float m_new = fmaxf(m_old, mx);
            float sum = 0.f;
#pragma unroll
            for (int c = 0; c < 16; c++) {
                float p = __expf(srow[seg * 16 + c] - m_new);
                srow[seg * 16 + c] = __uint_as_float(f2tf(p));
                sum += p;
            }
            sum += __shfl_xor_sync(0xffffffffu, sum, 1);
            sum += __shfl_xor_sync(0xffffffffu, sum, 2);
            if (seg == 0) {
                float alpha = __expf(m_old - m_new);
                l_sm[row] = l_sm[row] * alpha + sum;
                m_sm[row] = m_new;
                a_sm[row] = alpha;
            }
        }
        __syncthreads();

        {
            const int ra = mq * 16 + lq;
            float al0 = a_sm[ra], al1 = a_sm[ra + 8];
#pragma unroll
            for (int nt = 0; nt < 8; nt++) {
                O[nt][0] *= al0; O[nt][1] *= al0;
                O[nt][2] *= al1; O[nt][3] *= al1;
            }
#pragma unroll
            for (int ks = 0; ks < 64; ks += 8) {
                int c0 = ks + lr;
                uint32_t a0 = __float_as_uint(Ss[ra * SS_STR + c0]);
                uint32_t a1 = __float_as_uint(Ss[(ra + 8) * SS_STR + c0]);
                uint32_t a2 = __float_as_uint(Ss[ra * SS_STR + c0 + 4]);
                uint32_t a3 = __float_as_uint(Ss[(ra + 8) * SS_STR + c0 + 4]);
#pragma unroll
                for (int nt = 0; nt < 8; nt++) {
                    int n = wh * 64 + nt * 8 + lq;
                    uint32_t b0 = __float_as_uint(Vs[c0 * VS_STR + n]);
                    uint32_t b1 = __float_as_uint(Vs[(c0 + 4) * VS_STR + n]);
                    mma_tf32(O[nt], a0, a1, a2, a3, b0, b1);
                }
            }
        }
        __syncthreads();
    }

    {
        const int ra = mq * 16 + lq;
        float inv0 = 1.0f / l_sm[ra];
        float inv1 = 1.0f / l_sm[ra + 8];
        float* Cp = ctx + ((size_t)(b * 2048 + qt * 64)) * 4096 + h * 128;
#pragma unroll
        for (int nt = 0; nt < 8; nt++) {
            int c = wh * 64 + nt * 8 + 2 * lr;
            *(float2*)(Cp + (size_t)ra * 4096 + c)       = make_float2(O[nt][0] * inv0, O[nt][1] * inv0);
            *(float2*)(Cp + (size_t)(ra + 8) * 4096 + c) = make_float2(O[nt][2] * inv1, O[nt][3] * inv1);
        }
    }
}

// =========================================================================
// launcher
// =========================================================================
extern "C" void kernel_launch(void* const* d_in, const int* in_sizes, int n_in,
                              void* d_out, int out_size)
{
    const float* q  = (const float*)d_in[0];
    const float* k  = (const float*)d_in[1];
    const float* v  = (const float*)d_in[2];
    const float* Wq = (const float*)d_in[3];
    const float* Wk = (const float*)d_in[4];
    const float* Wv = (const float*)d_in[5];
    const float* Wd = (const float*)d_in[6];
    float* out = (float*)d_out;

    float *Qp, *Kp, *Vp, *Cp;
    cudaGetSymbolAddress((void**)&Qp, g_Q);
    cudaGetSymbolAddress((void**)&Kp, g_K);
    cudaGetSymbolAddress((void**)&Vp, g_V);
    cudaGetSymbolAddress((void**)&Cp, g_ctx);

    const int ATTN_SMEM = (2 * 64 * QS_STR + 64 * VS_STR + 64 * SS_STR + 192) * 4;
    cudaFuncSetAttribute(gemm_tf32,   cudaFuncAttributeMaxDynamicSharedMemorySize, GEMM_SMEM);
    cudaFuncSetAttribute(attn_kernel, cudaFuncAttributeMaxDynamicSharedMemorySize, ATTN_SMEM);

    // projections
    gemm_tf32<<<dim3(4096 / 128, 32), 256, GEMM_SMEM>>>(Qp, q, Wq, 4096, 4096, 4096);
    gemm_tf32<<<dim3(1024 / 128, 32), 256, GEMM_SMEM>>>(Kp, k, Wk, 4096, 1024, 4096);
    gemm_tf32<<<dim3(1024 / 128, 32), 256, GEMM_SMEM>>>(Vp, v, Wv, 4096, 1024, 4096);

    // RoPE (fused Q+K)
    rope_all<<<dim3(4096, 10), dim3(64, 4)>>>(Qp, Kp);

    // attention
    attn_kernel<<<dim3(32, 32, 2), 256, ATTN_SMEM>>>(Cp, Qp, Kp, Vp);

    // output projection
    gemm_tf32<<<dim3(4096 / 128, 32), 256, GEMM_SMEM>>>(out, Cp, Wd, 4096, 4096, 4096);
}

// round 7
// speedup vs baseline: 1.4735x; 1.4735x over previous
#include <cuda_runtime.h>
#include <cuda_fp16.h>
#include <cstdint>
#include <cstddef>

// ---------------- scratch ----------------
__device__ float g_Q[4096u * 4096u];
__device__ float g_K[4096u * 1024u];
__device__ float g_V[4096u * 1024u];
__device__ float g_ctx[4096u * 4096u];

// ---------------- helpers ----------------
__device__ __forceinline__ uint32_t f2tf(float x) {
    uint32_t u;
    asm("cvt.rna.tf32.f32 %0, %1;" : "=r"(u) : "f"(x));
    return u;
}
__device__ __forceinline__ float4 tf4(float4 v) {
    float4 t;
    t.x = __uint_as_float(f2tf(v.x)); t.y = __uint_as_float(f2tf(v.y));
    t.z = __uint_as_float(f2tf(v.z)); t.w = __uint_as_float(f2tf(v.w));
    return t;
}
__device__ __forceinline__ void mma_tf32(float* c, uint32_t a0, uint32_t a1,
                                         uint32_t a2, uint32_t a3,
                                         uint32_t b0, uint32_t b1) {
    asm volatile(
        "mma.sync.aligned.m16n8k8.row.col.f32.tf32.tf32.f32 "
        "{%0,%1,%2,%3}, {%4,%5,%6,%7}, {%8,%9}, {%0,%1,%2,%3};\n"
        : "+f"(c[0]), "+f"(c[1]), "+f"(c[2]), "+f"(c[3])
        : "r"(a0), "r"(a1), "r"(a2), "r"(a3), "r"(b0), "r"(b1));
}
__device__ __forceinline__ void mma_f16(float* c, uint32_t a0, uint32_t a1,
                                        uint32_t a2, uint32_t a3,
                                        uint32_t b0, uint32_t b1) {
    asm volatile(
        "mma.sync.aligned.m16n8k16.row.col.f32.f16.f16.f32 "
        "{%0,%1,%2,%3}, {%4,%5,%6,%7}, {%8,%9}, {%0,%1,%2,%3};\n"
        : "+f"(c[0]), "+f"(c[1]), "+f"(c[2]), "+f"(c[3])
        : "r"(a0), "r"(a1), "r"(a2), "r"(a3), "r"(b0), "r"(b1));
}

// =========================================================================
// FP16 GEMM:  C[M,N] = A[M,K] @ B[N,K]^T   (fp32 in/out, fp16 MMA, fp32 acc)
// Block 128x128, K-tile 32, 256 threads (8 warps: 2 in M x 4 in N),
// warp tile 64x32 = 4x4 mma(m16n8k16). Double-buffered smem (half2).
// Row stride 20 half2 (16 data + 4 pad) -> conflict-free fragment loads.
// =========================================================================
#define HS 20                            // half2 per row
#define GEMM_SMEM (2 * 2 * 128 * HS * 4) // 40960 bytes

__global__ void __launch_bounds__(256)
gemm_f16(float* __restrict__ C, const float* __restrict__ A,
         const float* __restrict__ B, int M, int N, int K)
{
    extern __shared__ __half2 smh[];
    __half2* AsBase = smh;                    // 2 * 128*20
    __half2* BsBase = smh + 2 * 128 * HS;     // 2 * 128*20

    const int tid  = threadIdx.x;
    const int warp = tid >> 5, lane = tid & 31;
    const int wm = warp & 1, wn = warp >> 1;
    const int bm = blockIdx.y * 128, bn = blockIdx.x * 128;
    const int kTiles = K >> 5;

    float acc[4][4][4];
#pragma unroll
    for (int i = 0; i < 4; i++)
#pragma unroll
        for (int j = 0; j < 4; j++)
#pragma unroll
            for (int t = 0; t < 4; t++) acc[i][j][t] = 0.f;

    float4 ra[4], rb[4];

    auto loadA = [&](int kt) {
        const float* Ag = A + (size_t)bm * K + (size_t)kt * 32;
#pragma unroll
        for (int i = 0; i < 4; i++) {
            int f = tid + i * 256;
            int r = f >> 3, c4 = (f & 7) << 2;
            ra[i] = *(const float4*)(Ag + (size_t)r * K + c4);
        }
    };
    auto loadB = [&](int kt) {
        const float* Bg = B + (size_t)bn * K + (size_t)kt * 32;
#pragma unroll
        for (int i = 0; i < 4; i++) {
            int f = tid + i * 256;
            int r = f >> 3, c4 = (f & 7) << 2;
            rb[i] = *(const float4*)(Bg + (size_t)r * K + c4);
        }
    };
    auto storeAB = [&](__half2* Ad, __half2* Bd) {
#pragma unroll
        for (int i = 0; i < 4; i++) {
            int f = tid + i * 256;
            int r = f >> 3, c8 = f & 7;
            __half2 a0 = __floats2half2_rn(ra[i].x, ra[i].y);
            __half2 a1 = __floats2half2_rn(ra[i].z, ra[i].w);
            __half2 b0 = __floats2half2_rn(rb[i].x, rb[i].y);
            __half2 b1 = __floats2half2_rn(rb[i].z, rb[i].w);
            __half2* pa = Ad + r * HS + c8 * 2;
            __half2* pb = Bd + r * HS + c8 * 2;
            pa[0] = a0; pa[1] = a1;
            pb[0] = b0; pb[1] = b1;
        }
    };
    auto compute = [&](const __half2* As_, const __half2* Bs_) {
#pragma unroll
        for (int ks = 0; ks < 2; ks++) {             // two k16 steps
            uint32_t a[4][4], b[4][2];
            const int c0 = ks * 8 + (lane & 3);
#pragma unroll
            for (int mt = 0; mt < 4; mt++) {
                int r0 = wm * 64 + mt * 16 + (lane >> 2);
                a[mt][0] = *(const uint32_t*)(As_ + r0 * HS + c0);
                a[mt][1] = *(const uint32_t*)(As_ + (r0 + 8) * HS + c0);
                a[mt][2] = *(const uint32_t*)(As_ + r0 * HS + c0 + 4);
                a[mt][3] = *(const uint32_t*)(As_ + (r0 + 8) * HS + c0 + 4);
            }
#pragma unroll
            for (int nt = 0; nt < 4; nt++) {
                int n0 = wn * 32 + nt * 8 + (lane >> 2);
                b[nt][0] = *(const uint32_t*)(Bs_ + n0 * HS + c0);
                b[nt][1] = *(const uint32_t*)(Bs_ + n0 * HS + c0 + 4);
            }
#pragma unroll
            for (int mt = 0; mt < 4; mt++)
#pragma unroll
                for (int nt = 0; nt < 4; nt++)
                    mma_f16(acc[mt][nt], a[mt][0], a[mt][1], a[mt][2], a[mt][3],
                            b[nt][0], b[nt][1]);
        }
    };

    loadA(0); loadB(0);
    storeAB(AsBase, BsBase);
    __syncthreads();

    for (int kt = 0; kt < kTiles; kt++) {
        int cur = kt & 1, nxt = cur ^ 1;
        if (kt + 1 < kTiles) { loadA(kt + 1); loadB(kt + 1); }
        compute(AsBase + cur * 128 * HS, BsBase + cur * 128 * HS);
        if (kt + 1 < kTiles)
            storeAB(AsBase + nxt * 128 * HS, BsBase + nxt * 128 * HS);
        __syncthreads();
    }

#pragma unroll
    for (int mt = 0; mt < 4; mt++) {
        int r0 = bm + wm * 64 + mt * 16 + (lane >> 2);
#pragma unroll
        for (int nt = 0; nt < 4; nt++) {
            int c0 = bn + wn * 32 + nt * 8 + ((lane & 3) << 1);
            float* c = acc[mt][nt];
            *(float2*)(C + (size_t)r0 * N + c0)       = make_float2(c[0], c[1]);
            *(float2*)(C + (size_t)(r0 + 8) * N + c0) = make_float2(c[2], c[3]);
        }
    }
}

// =========================================================================
// Fused RoPE: Q heads (0..31) and K heads (32..39), grid (4096,10), blk (64,4)
// =========================================================================
__global__ void rope_all(float* __restrict__ Q, float* __restrict__ K)
{
    int tok = blockIdx.x;
    int hh  = blockIdx.y * 4 + threadIdx.y;
    int d   = threadIdx.x;
    int s   = tok & 2047;
    float inv = exp2f((float)d * -0.20762050593046f);
    float ang = (float)s * inv;
    float sn, cs;
    sincosf(ang, &sn, &cs);
    float* p = (hh < 32) ? (Q + (size_t)tok * 4096 + hh * 128)
                         : (K + (size_t)tok * 1024 + (hh - 32) * 128);
    float x1 = p[d], x2 = p[d + 64];
    p[d]      = x1 * cs - x2 * sn;
    p[d + 64] = x2 * cs + x1 * sn;
}

// =========================================================================
// Causal flash attention with tf32 mma (unchanged — known-good)
// =========================================================================
#define QS_STR 132
#define VS_STR 136
#define SS_STR 68

__global__ void __launch_bounds__(256)
attn_kernel(float* __restrict__ ctx, const float* __restrict__ Qg,
            const float* __restrict__ Kg, const float* __restrict__ Vg)
{
    extern __shared__ float sm[];
    float* Qs   = sm;
    float* Ks   = Qs + 64 * QS_STR;
    float* Vs   = Ks + 64 * QS_STR;
    float* Ss   = Vs + 64 * VS_STR;
    float* m_sm = Ss + 64 * SS_STR;
    float* l_sm = m_sm + 64;
    float* a_sm = l_sm + 64;

    const int tid  = threadIdx.x;
    const int warp = tid >> 5, lane = tid & 31;
    const int lq = lane >> 2;
    const int lr = lane & 3;
    const int qt = 31 - (int)blockIdx.x;
    const int h  = blockIdx.y;
    const int b  = blockIdx.z;
    const int hkv = h >> 2;
    const float scale = 0.08838834764831845f;

    const int mq = warp & 3;
    const int wh = warp >> 2;

    const float* Qp = Qg + ((size_t)(b * 2048 + qt * 64)) * 4096 + h * 128;
#pragma unroll
    for (int i = 0; i < 8; i++) {
        int f = tid + i * 256;
        int r = f >> 5, c4 = (f & 31) << 2;
        float4 v = *(const float4*)(Qp + (size_t)r * 4096 + c4);
        v.x *= scale; v.y *= scale; v.z *= scale; v.w *= scale;
        *(float4*)(Qs + r * QS_STR + c4) = tf4(v);
    }
    if (tid < 64) { m_sm[tid] = -3.0e38f; l_sm[tid] = 0.f; }

    float O[8][4];
#pragma unroll
    for (int i = 0; i < 8; i++)
#pragma unroll
        for (int j = 0; j < 4; j++) O[i][j] = 0.f;

    __syncthreads();

    for (int kt = 0; kt <= qt; kt++) {
        const float* Kp = Kg + ((size_t)(b * 2048 + kt * 64)) * 1024 + hkv * 128;
        const float* Vp = Vg + ((size_t)(b * 2048 + kt * 64)) * 1024 + hkv * 128;
#pragma unroll
        for (int i = 0; i < 8; i++) {
            int f = tid + i * 256;
            int r = f >> 5, c4 = (f & 31) << 2;
            *(float4*)(Ks + r * QS_STR + c4) = tf4(*(const float4*)(Kp + (size_t)r * 1024 + c4));
            *(float4*)(Vs + r * VS_STR + c4) = tf4(*(const float4*)(Vp + (size_t)r * 1024 + c4));
        }
        __syncthreads();

        {
            float sacc[4][4];
#pragma unroll
            for (int nt = 0; nt < 4; nt++)
#pragma unroll
                for (int t = 0; t < 4; t++) sacc[nt][t] = 0.f;

            const int r0 = mq * 16 + lq;
#pragma unroll
            for (int ks = 0; ks < 128; ks += 8) {
                int c0 = ks + lr;
                uint32_t a0 = __float_as_uint(Qs[r0 * QS_STR + c0]);
                uint32_t a1 = __float_as_uint(Qs[(r0 + 8) * QS_STR + c0]);
                uint32_t a2 = __float_as_uint(Qs[r0 * QS_STR + c0 + 4]);
                uint32_t a3 = __float_as_uint(Qs[(r0 + 8) * QS_STR + c0 + 4]);
#pragma unroll
                for (int nt = 0; nt < 4; nt++) {
                    int n0 = wh * 32 + nt * 8 + lq;
                    uint32_t b0 = __float_as_uint(Ks[n0 * QS_STR + c0]);
                    uint32_t b1 = __float_as_uint(Ks[n0 * QS_STR + c0 + 4]);
                    mma_tf32(sacc[nt], a0, a1, a2, a3, b0, b1);
                }
            }
            bool diag = (kt == qt);
#pragma unroll
            for (int nt = 0; nt < 4; nt++) {
                int c = wh * 32 + nt * 8 + 2 * lr;
                float v0 = sacc[nt][0], v1 = sacc[nt][1];
                float v2 = sacc[nt][2], v3 = sacc[nt][3];
                int ra = mq * 16 + lq, rb2 = ra + 8;
                if (diag) {
                    if (c > ra)      v0 = -3.0e38f;
                    if (c + 1 > ra)  v1 = -3.0e38f;
                    if (c > rb2)     v2 = -3.0e38f;
                    if (c + 1 > rb2) v3 = -3.0e38f;
                }
                *(float2*)(Ss + ra * SS_STR + c)  = make_float2(v0, v1);
                *(float2*)(Ss + rb2 * SS_STR + c) = make_float2(v2, v3);
            }
        }
        __syncthreads();

        {
            int row = tid >> 2, seg = tid & 3;
            float* srow = Ss + row * SS_STR;
            float mx = -3.0e38f;
#pragma unroll
            for (int c = 0; c < 16; c++) mx = fmaxf(mx, srow[seg * 16 + c]);
            mx = fmaxf(mx, __shfl_xor_sync(0xffffffffu, mx, 1));
            mx = fmaxf(mx, __shfl_xor_sync(0xffffffffu, mx, 2));
            float m_old = m_sm[row];
            float m_new = fmaxf(m_old, mx);
            float sum = 0.f;
#pragma unroll
            for (int c = 0; c < 16; c++) {
                float p = __expf(srow[seg * 16 + c] - m_new);
                srow[seg * 16 + c] = __uint_as_float(f2tf(p));
                sum += p;
            }
            sum += __shfl_xor_sync(0xffffffffu, sum, 1);
            sum += __shfl_xor_sync(0xffffffffu, sum, 2);
            if (seg == 0) {
                float alpha = __expf(m_old - m_new);
                l_sm[row] = l_sm[row] * alpha + sum;
                m_sm[row] = m_new;
                a_sm[row] = alpha;
            }
        }
        __syncthreads();

        {
            const int ra = mq * 16 + lq;
            float al0 = a_sm[ra], al1 = a_sm[ra + 8];
#pragma unroll
            for (int nt = 0; nt < 8; nt++) {
                O[nt][0] *= al0; O[nt][1] *= al0;
                O[nt][2] *= al1; O[nt][3] *= al1;
            }
#pragma unroll
            for (int ks = 0; ks < 64; ks += 8) {
                int c0 = ks + lr;
                uint32_t a0 = __float_as_uint(Ss[ra * SS_STR + c0]);
                uint32_t a1 = __float_as_uint(Ss[(ra + 8) * SS_STR + c0]);
                uint32_t a2 = __float_as_uint(Ss[ra * SS_STR + c0 + 4]);
                uint32_t a3 = __float_as_uint(Ss[(ra + 8) * SS_STR + c0 + 4]);
#pragma unroll
                for (int nt = 0; nt < 8; nt++) {
                    int n = wh * 64 + nt * 8 + lq;
                    uint32_t b0 = __float_as_uint(Vs[c0 * VS_STR + n]);
                    uint32_t b1 = __float_as_uint(Vs[(c0 + 4) * VS_STR + n]);
                    mma_tf32(O[nt], a0, a1, a2, a3, b0, b1);
                }
            }
        }
        __syncthreads();
    }

    {
        const int ra = mq * 16 + lq;
        float inv0 = 1.0f / l_sm[ra];
        float inv1 = 1.0f / l_sm[ra + 8];
        float* Cp = ctx + ((size_t)(b * 2048 + qt * 64)) * 4096 + h * 128;
#pragma unroll
        for (int nt = 0; nt < 8; nt++) {
            int c = wh * 64 + nt * 8 + 2 * lr;
            *(float2*)(Cp + (size_t)ra * 4096 + c)       = make_float2(O[nt][0] * inv0, O[nt][1] * inv0);
            *(float2*)(Cp + (size_t)(ra + 8) * 4096 + c) = make_float2(O[nt][2] * inv1, O[nt][3] * inv1);
        }
    }
}

// =========================================================================
// launcher
// =========================================================================
extern "C" void kernel_launch(void* const* d_in, const int* in_sizes, int n_in,
                              void* d_out, int out_size)
{
    const float* q  = (const float*)d_in[0];
    const float* k  = (const float*)d_in[1];
    const float* v  = (const float*)d_in[2];
    const float* Wq = (const float*)d_in[3];
    const float* Wk = (const float*)d_in[4];
    const float* Wv = (const float*)d_in[5];
    const float* Wd = (const float*)d_in[6];
    float* out = (float*)d_out;

    float *Qp, *Kp, *Vp, *Cp;
    cudaGetSymbolAddress((void**)&Qp, g_Q);
    cudaGetSymbolAddress((void**)&Kp, g_K);
    cudaGetSymbolAddress((void**)&Vp, g_V);
    cudaGetSymbolAddress((void**)&Cp, g_ctx);

    const int ATTN_SMEM = (2 * 64 * QS_STR + 64 * VS_STR + 64 * SS_STR + 192) * 4;
    cudaFuncSetAttribute(gemm_f16,    cudaFuncAttributeMaxDynamicSharedMemorySize, GEMM_SMEM);
    cudaFuncSetAttribute(attn_kernel, cudaFuncAttributeMaxDynamicSharedMemorySize, ATTN_SMEM);

    // projections
    gemm_f16<<<dim3(4096 / 128, 32), 256, GEMM_SMEM>>>(Qp, q, Wq, 4096, 4096, 4096);
    gemm_f16<<<dim3(1024 / 128, 32), 256, GEMM_SMEM>>>(Kp, k, Wk, 4096, 1024, 4096);
    gemm_f16<<<dim3(1024 / 128, 32), 256, GEMM_SMEM>>>(Vp, v, Wv, 4096, 1024, 4096);

    // RoPE (fused Q+K)
    rope_all<<<dim3(4096, 10), dim3(64, 4)>>>(Qp, Kp);

    // attention
    attn_kernel<<<dim3(32, 32, 2), 256, ATTN_SMEM>>>(Cp, Qp, Kp, Vp);

    // output projection
    gemm_f16<<<dim3(4096 / 128, 32), 256, GEMM_SMEM>>>(out, Cp, Wd, 4096, 4096, 4096);
}